// round 17
// baseline (speedup 1.0000x reference)
#include <cuda_runtime.h>

#define TPB  256
#define PPT  4
#define TILE (TPB * PPT)   // 1024 points per block
#define G    256           // LUT grid resolution

// Winner LUT: g_lut[sx*G+sy] = winner+1 (0 = black) if the whole cell provably
// has a constant winner, else 255 (ambiguous -> exact slow path).
__device__ unsigned char g_lut[G * G];

// ---------------------------------------------------------------------------
// Interval helpers (setup kernel only; conservative, margins >> f32 rounding)
// ---------------------------------------------------------------------------
__device__ __forceinline__ void imul(float lo, float hi, float c,
                                     float& rlo, float& rhi) {
    float a = lo * c, b = hi * c;
    rlo = fminf(a, b); rhi = fmaxf(a, b);
}
__device__ __forceinline__ void isq(float lo, float hi,
                                    float& rlo, float& rhi) {
    float a = lo * lo, b = hi * hi;
    rlo = (lo <= 0.0f && hi >= 0.0f) ? 0.0f : fminf(a, b);
    rhi = fmaxf(a, b);
}

// ---------------------------------------------------------------------------
// Setup: build the winner LUT (smem-staged params + bbox pre-reject)
// ---------------------------------------------------------------------------
__global__ void lut_kernel(const float* __restrict__ p)
{
    __shared__ float sp[700];
    __shared__ float bbx0[75], bbx1[75], bby0[75], bby1[75];

    const int tid = threadIdx.x;
    for (int i = tid; i < 700; i += 256) sp[i] = p[i];
    __syncthreads();

    if (tid < 75) {
        int c = tid / 3, t = tid - 3 * c;
        const float* q = sp + c * 28;
        float x0, x1, y0, y1;
        if (t == 0) {
            x0 = fminf(q[1], fminf(q[3], q[5]));
            x1 = fmaxf(q[1], fmaxf(q[3], q[5]));
            y0 = fminf(q[2], fminf(q[4], q[6]));
            y1 = fmaxf(q[2], fmaxf(q[4], q[6]));
        } else if (t == 1) {
            x0 = q[12] - q[14]; x1 = q[12] + q[14];
            y0 = q[13] - q[14]; y1 = q[13] + q[14];
        } else {
            x0 = q[20] - q[22]; x1 = q[20] + q[22];
            y0 = q[21] - q[23]; y1 = q[21] + q[23];
        }
        // Expansion 1e-5 >> f32 boundary-rounding band (~1e-6): bbox-reject
        // implies certainly-outside for every point of any rejected rect.
        const float E = 1e-5f;
        bbx0[tid] = x0 - E; bbx1[tid] = x1 + E;
        bby0[tid] = y0 - E; bby1[tid] = y1 + E;
    }
    __syncthreads();

    int cid = blockIdx.x * blockDim.x + tid;
    int sx = cid >> 8, sy = cid & (G - 1);

    const float inv = 1.0f / (float)G;
    // Rect expanded by 1e-6 to cover point->cell assignment rounding slop.
    float xlo = sx * inv - 1e-6f, xhi = (sx + 1) * inv + 1e-6f;
    float ylo = sy * inv - 1e-6f, yhi = (sy + 1) * inv + 1e-6f;

    // Candidate macro cells: shapes reach <= 0.08 (+slop) outside their cell.
    int i0 = (int)floorf((xlo - 0.0812f) * 5.0f); i0 = i0 < 0 ? 0 : i0;
    int i1 = (int)floorf((xhi + 0.0812f) * 5.0f); i1 = i1 > 4 ? 4 : i1;
    int j0 = (int)floorf((ylo - 0.0812f) * 5.0f); j0 = j0 < 0 ? 0 : j0;
    int j1 = (int)floorf((yhi + 0.0812f) * 5.0f); j1 = j1 > 4 ? 4 : j1;

    const float D = 2e-6f;   // absolute slack >> accumulated f32 rounding
    int best = -1, amb = -1;

    for (int i = i0; i <= i1; i++) {
        for (int j = j0; j <= j1; j++) {
            int cell = i * 5 + j;
            const float* q = sp + cell * 28;
            int c3 = cell * 3;

            // ---- triangle (shape id c3) ----
            if (!(xhi < bbx0[c3] || xlo > bbx1[c3] ||
                  yhi < bby0[c3] || ylo > bby1[c3])) {
                float ax = q[1], ay = q[2], bx = q[3], by = q[4];
                float cx = q[5], cy = q[6];
                float vx[3] = {ax, bx, cx}, vy[3] = {ay, by, cy};
                float dx[3] = {bx - ax, cx - bx, ax - cx};
                float dy[3] = {by - ay, cy - by, ay - cy};
                int npos = 0, nneg = 0;
                for (int e = 0; e < 3; e++) {
                    float alo, ahi, blo, bhi;
                    imul(xlo - vx[e], xhi - vx[e], dy[e], alo, ahi);
                    imul(ylo - vy[e], yhi - vy[e], dx[e], blo, bhi);
                    float elo = alo - bhi - D, ehi = ahi - blo + D;
                    if (elo > 0.0f) npos++;
                    else if (ehi < 0.0f) nneg++;
                }
                if (npos == 3 || nneg == 3)          best = max(best, c3);
                else if (!(npos >= 1 && nneg >= 1))  amb  = max(amb, c3);
            }
            // ---- circle (shape id c3+1) ----
            if (!(xhi < bbx0[c3 + 1] || xlo > bbx1[c3 + 1] ||
                  yhi < bby0[c3 + 1] || ylo > bby1[c3 + 1])) {
                float ox = q[12], oy = q[13], r = q[14];
                float r2 = r * r;
                float ulo, uhi, vlo, vhi;
                isq(xlo - ox, xhi - ox, ulo, uhi);
                isq(ylo - oy, yhi - oy, vlo, vhi);
                float glo = ulo + vlo - r2 - D, ghi = uhi + vhi - r2 + D;
                if (ghi <= 0.0f)        best = max(best, c3 + 1);
                else if (!(glo > 0.0f)) amb  = max(amb, c3 + 1);
            }
            // ---- ellipse (shape id c3+2) ----
            if (!(xhi < bbx0[c3 + 2] || xlo > bbx1[c3 + 2] ||
                  yhi < bby0[c3 + 2] || ylo > bby1[c3 + 2])) {
                float ex = q[20], ey = q[21];
                float irx = 1.0f / q[22], iry = 1.0f / q[23];
                float alo, ahi, blo, bhi, slo, shi, tlo, thi;
                imul(xlo - ex, xhi - ex, irx, alo, ahi); isq(alo, ahi, slo, shi);
                imul(ylo - ey, yhi - ey, iry, blo, bhi); isq(blo, bhi, tlo, thi);
                float glo = slo + tlo - 1.0f - D, ghi = shi + thi - 1.0f + D;
                if (ghi <= 0.0f)        best = max(best, c3 + 2);
                else if (!(glo > 0.0f)) amb  = max(amb, c3 + 2);
            }
        }
    }
    g_lut[cid] = (amb <= best) ? (unsigned char)(best + 1)
                               : (unsigned char)255;
}

// ---------------------------------------------------------------------------
// Main kernel: LUT fast path + exact compacted slow path (bit-exact R11 math)
// ---------------------------------------------------------------------------
// Cell record (13 floats): 3 x float4 + 1 scalar
//  r0: ax, ay, bx, by
//  r1: cx, cy, ocx, ocy
//  r2: r*r, ecx, ecy, 1/erx
//  siery: 1/ery
#define SHADE_CELL(cell)                                                       \
    do {                                                                       \
        int _c = (cell);                                                       \
        float4 r0  = rec4[_c * 3 + 0];                                         \
        float4 r1  = rec4[_c * 3 + 1];                                         \
        float4 r2v = rec4[_c * 3 + 2];                                         \
        float  iery = siery[_c];                                               \
        float d0x = __fsub_rn(r0.z, r0.x), d0y = __fsub_rn(r0.w, r0.y);        \
        float d1x = __fsub_rn(r1.x, r0.z), d1y = __fsub_rn(r1.y, r0.w);        \
        float d2x = __fsub_rn(r0.x, r1.x), d2y = __fsub_rn(r0.y, r1.y);        \
        float e0 = __fsub_rn(__fmul_rn(__fsub_rn(px, r0.x), d0y),              \
                             __fmul_rn(__fsub_rn(py, r0.y), d0x));             \
        float e1 = __fsub_rn(__fmul_rn(__fsub_rn(px, r0.z), d1y),              \
                             __fmul_rn(__fsub_rn(py, r0.w), d1x));             \
        float e2 = __fsub_rn(__fmul_rn(__fsub_rn(px, r1.x), d2y),              \
                             __fmul_rn(__fsub_rn(py, r1.y), d2x));             \
        float emin = fminf(fminf(e0, e1), e2);                                 \
        float emax = fmaxf(fmaxf(e0, e1), e2);                                 \
        bool tri_in = (emin >= 0.0f) || (emax <= 0.0f);                        \
        float dcx = __fsub_rn(px, r1.z), dcy = __fsub_rn(py, r1.w);            \
        bool circ_in =                                                         \
            __fadd_rn(__fmul_rn(dcx, dcx), __fmul_rn(dcy, dcy)) <= r2v.x;      \
        float xn = __fmul_rn(__fsub_rn(px, r2v.y), r2v.w);                     \
        float yn = __fmul_rn(__fsub_rn(py, r2v.z), iery);                      \
        bool ell_in =                                                          \
            __fadd_rn(__fmul_rn(xn, xn), __fmul_rn(yn, yn)) <= 1.0f;           \
        int c3 = _c * 3;                                                       \
        int cb = tri_in ? c3 : -1;                                             \
        cb = circ_in ? c3 + 1 : cb;                                            \
        cb = ell_in ? c3 + 2 : cb;                                             \
        best = best > cb ? best : cb;                                          \
    } while (0)

__global__ __launch_bounds__(TPB, 8)
void vg_kernel(const float* __restrict__ x, const float* __restrict__ p,
               float* __restrict__ out, int n)
{
    __shared__ float4 rec4[25 * 3];
    __shared__ float  siery[25];
    __shared__ float4 colors4[76];         // slot 0 = black
    __shared__ unsigned char sbest[TILE];  // winner+1 per tile point
    __shared__ float2 qpt[TILE];           // ambiguous-point queue
    __shared__ unsigned short qli[TILE];
    __shared__ int qcnt;

    const int tid = threadIdx.x;

    if (tid < 25) {
        const float* q = p + tid * 28;
        rec4[tid * 3 + 0] = make_float4(q[1], q[2], q[3], q[4]);
        rec4[tid * 3 + 1] = make_float4(q[5], q[6], q[12], q[13]);
        rec4[tid * 3 + 2] = make_float4(__fmul_rn(q[14], q[14]),
                                        q[20], q[21], 1.0f / q[22]);
        siery[tid] = 1.0f / q[23];
    }
    if (tid < 76) {
        if (tid == 0) colors4[0] = make_float4(0.0f, 0.0f, 0.0f, 0.0f);
        else {
            int s = tid - 1;
            int c = s / 3, t = s % 3;
            int o = (t == 0) ? 8 : ((t == 1) ? 16 : 25);
            const float* q = p + c * 28 + o;
            colors4[tid] = make_float4(q[0], q[1], q[2], 0.0f);
        }
    }
    if (tid == 0) qcnt = 0;
    __syncthreads();

    const int base = blockIdx.x * TILE;

    // ---- Fast path: thread owns 4 CONSECUTIVE points; packed STS.32 ----
    {
        const float4* x4 = (const float4*)x;   // one float4 = 2 points
        int nv = n >> 1;
        int i0 = (base >> 1) + 2 * tid;        // pairs (4t..4t+1), (4t+2..4t+3)
        float4 a = (i0     < nv) ? x4[i0]     : make_float4(0.5f, 0.5f, 0.5f, 0.5f);
        float4 b = (i0 + 1 < nv) ? x4[i0 + 1] : make_float4(0.5f, 0.5f, 0.5f, 0.5f);
        float2 pts[PPT];
        pts[0] = make_float2(a.x, a.y);
        pts[1] = make_float2(a.z, a.w);
        pts[2] = make_float2(b.x, b.y);
        pts[3] = make_float2(b.z, b.w);

        unsigned pack = 0;
#pragma unroll
        for (int k = 0; k < PPT; k++) {
            float2 pt = pts[k];
            int sx = (int)(pt.x * 256.0f); sx = sx < 0 ? 0 : (sx > 255 ? 255 : sx);
            int sy = (int)(pt.y * 256.0f); sy = sy < 0 ? 0 : (sy > 255 ? 255 : sy);
            unsigned w = g_lut[(sx << 8) | sy];
            if (w == 255u) {
                int qi = atomicAdd(&qcnt, 1);
                qpt[qi] = pt;
                qli[qi] = (unsigned short)(4 * tid + k);
                w = 0u;
            }
            pack |= w << (8 * k);
        }
        ((unsigned*)sbest)[tid] = pack;    // conflict-free aligned STS.32
    }
    __syncthreads();

    // ---- Slow path: exact shading for ambiguous points ----
    {
        int qn = qcnt;
        for (int i = tid; i < qn; i += TPB) {
            float2 pt = qpt[i];
            const float px = pt.x, py = pt.y;
            // 1/16-cell classifier: thresholds 7/16 and 9/16 bracket the
            // true 0.4 cell-width shape overhang with >=0.0375cw margin.
            int sx = (int)(px * 80.0f); sx = sx < 0 ? 0 : (sx > 79 ? 79 : sx);
            int sy = (int)(py * 80.0f); sy = sy < 0 ? 0 : (sy > 79 ? 79 : sy);
            int ci = sx >> 4, fx = sx & 15;
            int cj = sy >> 4, fy = sy & 15;
            int dxn = (fx <= 6) ? -1 : ((fx >= 9) ? 1 : 0);
            int dyn = (fy <= 6) ? -1 : ((fy >= 9) ? 1 : 0);
            int cc = ci * 5 + cj;
            int i2 = ci + dxn, j2 = cj + dyn;
            int ccx  = ((unsigned)i2 <= 4u) ? cc + dxn * 5 : cc;  // dup-clamp
            int ccy  = ((unsigned)j2 <= 4u) ? cc + dyn     : cc;
            int ccxy = ccx + (ccy - cc);

            int best = -1;
            SHADE_CELL(cc);
            SHADE_CELL(ccx);
            SHADE_CELL(ccy);
            SHADE_CELL(ccxy);

            sbest[qli[i]] = (unsigned char)(best + 1);
        }
    }
    __syncthreads();

    // ---- Output: uchar4 winners -> 3 x STG.128 per thread ----
    {
        int gi0 = base + tid * 4;
        if (gi0 + 4 <= n) {
            uchar4 u = ((const uchar4*)sbest)[tid];
            float4 C0 = colors4[u.x];
            float4 C1 = colors4[u.y];
            float4 C2 = colors4[u.z];
            float4 C3 = colors4[u.w];
            float4* dst = (float4*)(out + (size_t)gi0 * 3);
            dst[0] = make_float4(C0.x, C0.y, C0.z, C1.x);
            dst[1] = make_float4(C1.y, C1.z, C2.x, C2.y);
            dst[2] = make_float4(C2.z, C3.x, C3.y, C3.z);
        } else {
            for (int k = 0; k < 4; k++) {
                int gi = gi0 + k;
                if (gi < n) {
                    float4 C = colors4[sbest[tid * 4 + k]];
                    out[gi * 3 + 0] = C.x;
                    out[gi * 3 + 1] = C.y;
                    out[gi * 3 + 2] = C.z;
                }
            }
        }
    }
}

extern "C" void kernel_launch(void* const* d_in, const int* in_sizes, int n_in,
                              void* d_out, int out_size)
{
    // Identify inputs robustly: x has 2*N elements, p has 700
    int xi = 0, pi = 1;
    if (n_in >= 2 && in_sizes[0] < in_sizes[1]) { xi = 1; pi = 0; }
    const float* x = (const float*)d_in[xi];
    const float* p = (const float*)d_in[pi];
    float* out = (float*)d_out;

    int n = in_sizes[xi] / 2;

    lut_kernel<<<G * G / 256, 256>>>(p);
    int blocks = (n + TILE - 1) / TILE;
    vg_kernel<<<blocks, TPB>>>(x, p, out, n);
}